// round 14
// baseline (speedup 1.0000x reference)
#include <cuda_runtime.h>

#define H 512
#define W 512
#define HW (H * W)
#define BN_EPS 1e-5f
#define RING (4 * W - 4)          // 2044 ring pixels per batch
#define BPX 14                    // border pixels per border block (14*9=126 thr)
#define NBY_MAIN 32               // 512 / 16 rows per main block
#define NBY_EXTRA 10              // 160 border blocks per batch (need 146)

typedef unsigned long long u64;

// Staging (written by prep_kernel) -> copied into __constant__ each launch.
// Layout per tap (12 floats): w0..w7, w8, w8, 0, 0   (slot9 = dup of w8)
//   [0,900)    5x5 weights, 75 taps x 12
//   [900,1224) 3x3 weights, 27 taps x 12
//   [1224,1232) BN shift pairs (8 floats = 4 u64)
//   [1232]     shift[8]
__device__ float g_stage[1236];
__constant__ __align__(16) float c_all[1236];

// ---------------- packed f32x2 helpers ----------------
__device__ __forceinline__ u64 pk(float a, float b) {
    u64 d;
    asm("mov.b64 %0, {%1, %2};" : "=l"(d) : "f"(a), "f"(b));
    return d;
}
__device__ __forceinline__ void upk(u64 d, float& a, float& b) {
    asm("mov.b64 {%0, %1}, %2;" : "=f"(a), "=f"(b) : "l"(d));
}
__device__ __forceinline__ void fma2(u64& c, u64 a, u64 b) {
    asm("fma.rn.f32x2 %0, %1, %2, %0;" : "+l"(c) : "l"(a), "l"(b));
}

// ---------------------------------------------------------------------------
// Kernel 1: prep — one staged entry per thread (10 blocks x 128 >= 1236).
// ---------------------------------------------------------------------------
__global__ void prep_kernel(const float* __restrict__ cw,
                            const float* __restrict__ gam,
                            const float* __restrict__ bet,
                            const float* __restrict__ mu,
                            const float* __restrict__ var) {
    int tid = blockIdx.x * blockDim.x + threadIdx.x;
    if (tid < 900) {
        int t5 = tid / 12, kk = tid % 12;
        if (kk >= 10) { g_stage[tid] = 0.f; return; }
        int k = (kk == 9) ? 8 : kk;             // slot 9 duplicates w8
        int v = t5 % 5, u = (t5 / 5) % 5, c = t5 / 25;
        float s = gam[k] * rsqrtf(var[k] + BN_EPS);
        float sum = 0.f;
#pragma unroll
        for (int ti = 0; ti < 3; ti++) {
            int di = u - ti;
            if (di < 0 || di > 2) continue;
#pragma unroll
            for (int tj = 0; tj < 3; tj++) {
                int dj = v - tj;
                if (dj < 0 || dj > 2) continue;
                int t = ti * 3 + tj;
                if (c == 0 && t >= 4 && t <= 6) continue;   // replaced rows
                sum += cw[((k * 27 + c * 9 + t) * 3 + di) * 3 + dj];
            }
        }
        g_stage[tid] = s * sum;
    } else if (tid < 1224) {
        int i = tid - 900;
        int t3 = i / 12, kk = i % 12;
        if (kk >= 10) { g_stage[tid] = 0.f; return; }
        int k = (kk == 9) ? 8 : kk;
        int v = t3 % 3, u = (t3 / 3) % 3, j = t3 / 9;
        float s = gam[k] * rsqrtf(var[k] + BN_EPS);
        g_stage[tid] = s * cw[((k * 27 + 4 + j) * 3 + u) * 3 + v];
    } else if (tid < 1233) {
        int k = tid - 1224;     // 0..8
        float s = gam[k] * rsqrtf(var[k] + BN_EPS);
        g_stage[tid] = bet[k] - mu[k] * s;
    } else if (tid < 1236) {
        g_stage[tid] = 0.f;
    }
}

// ---------------------------------------------------------------------------
// Row loaders over window [w0-2, w0+5].
//   dup[i] = {v[i], v[i]}   (broadcast data, for k0..7 packed weight pairs)
//   adj[i] = {v[i], v[i+1]} (adjacent-pixel pairs, for packed k8)
// ---------------------------------------------------------------------------
__device__ __forceinline__ void build_pairs(const float v[8], u64 dup[8], u64 adj[7]) {
#pragma unroll
    for (int i = 0; i < 8; i++) dup[i] = pk(v[i], v[i]);
#pragma unroll
    for (int i = 0; i < 7; i++) adj[i] = pk(v[i], v[i + 1]);
}

__device__ __forceinline__ void load_row8_fast(const float* __restrict__ p,
                                               u64 dup[8], u64 adj[7]) {
    float v[8];
    u64 a = *(const u64*)(p - 2);          // v0,v1
    float4 m = *(const float4*)(p);        // v2..v5 (16B aligned)
    u64 c = *(const u64*)(p + 4);          // v6,v7
    upk(a, v[0], v[1]);
    v[2] = m.x; v[3] = m.y; v[4] = m.z; v[5] = m.w;
    upk(c, v[6], v[7]);
    build_pairs(v, dup, adj);
}

__device__ __forceinline__ void load_row8_guard(const float* __restrict__ rowp, int w0,
                                                bool rowok, bool colsafe,
                                                u64 dup[8], u64 adj[7]) {
    if (rowok && colsafe) {
        load_row8_fast(rowp + w0, dup, adj);
        return;
    }
    float v[8];
    if (rowok) {
#pragma unroll
        for (int i = 0; i < 8; i++) {
            int ww = w0 - 2 + i;
            v[i] = (ww >= 0 && ww < W) ? rowp[ww] : 0.f;
        }
    } else {
#pragma unroll
        for (int i = 0; i < 8; i++) v[i] = 0.f;
    }
    build_pairs(v, dup, adj);
}

// Apply one tap's 9 weights from __constant__ at float-offset woff.
// k0..7: packed weight pairs x broadcast data; k8: dup'd weight x pixel pairs.
__device__ __forceinline__ void apply_tap_c(int woff,
                                            const u64 dup[8], const u64 adj[7], int base,
                                            u64 accp[4][4], u64 acc8p[2]) {
    ulonglong2 qa = *(const ulonglong2*)&c_all[woff];       // {w0,w1},{w2,w3}
    ulonglong2 qb = *(const ulonglong2*)&c_all[woff + 4];   // {w4,w5},{w6,w7}
    u64 w8d = *(const u64*)&c_all[woff + 8];                // {w8,w8}
#pragma unroll
    for (int p = 0; p < 4; p++) {
        u64 d = dup[base + p];
        fma2(accp[p][0], qa.x, d);
        fma2(accp[p][1], qa.y, d);
        fma2(accp[p][2], qb.x, d);
        fma2(accp[p][3], qb.y, d);
    }
    fma2(acc8p[0], w8d, adj[base]);       // pixels (0,1)
    fma2(acc8p[1], w8d, adj[base + 2]);   // pixels (2,3)
}

// ---------------------------------------------------------------------------
// Kernel 2: fused main + border.
// ---------------------------------------------------------------------------
__global__ __launch_bounds__(128, 6) void cspn_main(
        const float* __restrict__ ker,
        const float* __restrict__ in,
        const float* __restrict__ in0,
        const float* __restrict__ cw,
        const float* __restrict__ gam,
        const float* __restrict__ bet,
        const float* __restrict__ mu,
        const float* __restrict__ var,
        float* __restrict__ out) {
    const int b = blockIdx.z;
    const int tid = threadIdx.y * 8 + threadIdx.x;

    if (blockIdx.y >= NBY_MAIN) {
        // ================= border path =================
        const int bidx = (blockIdx.y - NBY_MAIN) * 16 + blockIdx.x;
        const int base = bidx * BPX;
        if (base >= RING) return;    // dead block (block-uniform)

        __shared__ float sw[2187];
        __shared__ float pacc[BPX * 9 * 9];

        for (int i = tid; i < 2187; i += 128) sw[i] = cw[i];
        __syncthreads();

        const int px   = tid / 9;
        const int didx = tid % 9;
        const int pos  = base + px;
        const bool active = (tid < 126) && (pos < RING);

        float acc[9];
#pragma unroll
        for (int k = 0; k < 9; k++) acc[k] = 0.f;

        if (active) {
            int h, w;
            if (pos < W)          { h = 0;     w = pos; }
            else if (pos < 2 * W) { h = H - 1; w = pos - W; }
            else {
                int p2 = pos - 2 * W;
                h = 1 + (p2 >> 1);
                w = (p2 & 1) ? (W - 1) : 0;
            }
            const float* inb  = in  + (size_t)b * 3 * HW;
            const float* in0b = in0 + (size_t)b * 3 * HW;
            const int dy = didx / 3 - 1, dx = didx % 3 - 1;
            const int qy = h + dy, qx = w + dx;
            const bool qok = (qy >= 0 && qy < H && qx >= 0 && qx < W);
#pragma unroll
            for (int ch = 0; ch < 27; ch++) {
                float val;
                if (ch >= 4 && ch <= 6) {
                    val = qok ? in0b[(ch - 4) * HW + qy * W + qx] : 0.f;
                } else {
                    int c = ch / 9, t = ch % 9;
                    int py = qy + t / 3 - 1, qx2 = qx + t % 3 - 1;
                    bool pok = qok && (py >= 0 && py < H && qx2 >= 0 && qx2 < W);
                    val = pok ? inb[c * HW + py * W + qx2] : 0.f;
                }
#pragma unroll
                for (int k = 0; k < 9; k++)
                    acc[k] = fmaf(sw[(k * 27 + ch) * 9 + didx], val, acc[k]);
            }
        }
        if (tid < 126) {
#pragma unroll
            for (int k = 0; k < 9; k++) pacc[(px * 9 + didx) * 9 + k] = acc[k];
        }
        __syncthreads();

        if (tid < BPX) {
            int pos2 = base + tid;
            if (pos2 < RING) {
                int hh, ww;
                if (pos2 < W)          { hh = 0;     ww = pos2; }
                else if (pos2 < 2 * W) { hh = H - 1; ww = pos2 - W; }
                else {
                    int p2 = pos2 - 2 * W;
                    hh = 1 + (p2 >> 1);
                    ww = (p2 & 1) ? (W - 1) : 0;
                }
                float r = 0.f;
#pragma unroll
                for (int k = 0; k < 9; k++) {
                    float s = 0.f;
#pragma unroll
                    for (int d = 0; d < 9; d++) s += pacc[(tid * 9 + d) * 9 + k];
                    float sc = gam[k] * rsqrtf(var[k] + BN_EPS);
                    float sh = bet[k] - mu[k] * sc;
                    r = fmaf(ker[((size_t)b * 9 + k) * HW + hh * W + ww],
                             fmaf(sc, s, sh), r);
                }
                out[(size_t)b * HW + hh * W + ww] = r;
            }
        }
        return;
    }

    // ================= main path (weights from __constant__) =================
    const int h  = blockIdx.y * 16 + threadIdx.y;
    const int w0 = blockIdx.x * 32 + threadIdx.x * 4;

    // Seed accumulators with the BN shift (deletes the epilogue adds).
    u64 accp[4][4];
    u64 acc8p[2];
    {
        u64 s0 = *(const u64*)&c_all[1224];
        u64 s1 = *(const u64*)&c_all[1226];
        u64 s2 = *(const u64*)&c_all[1228];
        u64 s3 = *(const u64*)&c_all[1230];
        float sh8 = c_all[1232];
        u64 s8 = pk(sh8, sh8);
#pragma unroll
        for (int p = 0; p < 4; p++) {
            accp[p][0] = s0; accp[p][1] = s1; accp[p][2] = s2; accp[p][3] = s3;
        }
        acc8p[0] = s8; acc8p[1] = s8;
    }

    const float* inb  = in  + (size_t)b * 3 * HW;
    const float* in0b = in0 + (size_t)b * 3 * HW;

    const bool fast = (blockIdx.x >= 1) && (blockIdx.x <= (W / 32) - 2) &&
                      (blockIdx.y >= 1) && (blockIdx.y <= NBY_MAIN - 2);

    if (fast) {
        const float* base5 = inb + (h - 2) * W + w0;
#pragma unroll
        for (int c = 0; c < 3; c++) {
#pragma unroll
            for (int u = 0; u < 5; u++) {
                u64 dup[8], adj[7];
                load_row8_fast(base5 + c * HW + u * W, dup, adj);
#pragma unroll
                for (int tv = 0; tv < 5; tv++)
                    apply_tap_c(((c * 5 + u) * 5 + tv) * 12, dup, adj, tv, accp, acc8p);
            }
        }
        const float* base3 = in0b + (h - 1) * W + w0;
#pragma unroll
        for (int j3 = 0; j3 < 3; j3++) {
#pragma unroll
            for (int u = 0; u < 3; u++) {
                u64 dup[8], adj[7];
                load_row8_fast(base3 + j3 * HW + u * W, dup, adj);
#pragma unroll
                for (int tv = 0; tv < 3; tv++)
                    apply_tap_c(900 + ((j3 * 3 + u) * 3 + tv) * 12, dup, adj, 1 + tv, accp, acc8p);
            }
        }
    } else {
        const bool colsafe = (w0 >= 2) && (w0 + 6 <= W);
#pragma unroll
        for (int c = 0; c < 3; c++) {
            const float* inc = inb + c * HW;
#pragma unroll
            for (int u = 0; u < 5; u++) {
                int r = h + u - 2;
                u64 dup[8], adj[7];
                load_row8_guard(inc + r * W, w0, (r >= 0 && r < H), colsafe, dup, adj);
#pragma unroll
                for (int tv = 0; tv < 5; tv++)
                    apply_tap_c(((c * 5 + u) * 5 + tv) * 12, dup, adj, tv, accp, acc8p);
            }
        }
#pragma unroll
        for (int j3 = 0; j3 < 3; j3++) {
            const float* inc = in0b + j3 * HW;
#pragma unroll
            for (int u = 0; u < 3; u++) {
                int r = h + u - 1;
                u64 dup[8], adj[7];
                load_row8_guard(inc + r * W, w0, (r >= 0 && r < H), colsafe, dup, adj);
#pragma unroll
                for (int tv = 0; tv < 3; tv++)
                    apply_tap_c(900 + ((j3 * 3 + u) * 3 + tv) * 12, dup, adj, 1 + tv, accp, acc8p);
            }
        }
    }

    // ---- epilogue: per-pixel dot with kernel (shift already in acc) ----
    const float* kp = ker + (size_t)b * 9 * HW + h * W + w0;
    u64 rp[4] = {0ull, 0ull, 0ull, 0ull};
#pragma unroll
    for (int j = 0; j < 4; j++) {
        const float4 ka = *(const float4*)(kp + (2 * j) * HW);
        const float4 kb = *(const float4*)(kp + (2 * j + 1) * HW);
        fma2(rp[0], pk(ka.x, kb.x), accp[0][j]);
        fma2(rp[1], pk(ka.y, kb.y), accp[1][j]);
        fma2(rp[2], pk(ka.z, kb.z), accp[2][j]);
        fma2(rp[3], pk(ka.w, kb.w), accp[3][j]);
    }
    float res[4];
    {
        const float4 k8 = *(const float4*)(kp + 8 * HW);
        float a80, a81, a82, a83;
        upk(acc8p[0], a80, a81);
        upk(acc8p[1], a82, a83);
        float lo, hi;
        upk(rp[0], lo, hi); res[0] = lo + hi + k8.x * a80;
        upk(rp[1], lo, hi); res[1] = lo + hi + k8.y * a81;
        upk(rp[2], lo, hi); res[2] = lo + hi + k8.z * a82;
        upk(rp[3], lo, hi); res[3] = lo + hi + k8.w * a83;
    }

    // Interior writes only (ring owned by border blocks).
    if (h >= 1 && h <= H - 2) {
        float* op = out + (size_t)b * HW + h * W + w0;
        if (w0 == 0)          { op[1] = res[1]; op[2] = res[2]; op[3] = res[3]; }
        else if (w0 == W - 4) { op[0] = res[0]; op[1] = res[1]; op[2] = res[2]; }
        else                  { *(float4*)op = make_float4(res[0], res[1], res[2], res[3]); }
    }
}

// ---------------------------------------------------------------------------
extern "C" void kernel_launch(void* const* d_in, const int* in_sizes, int n_in,
                              void* d_out, int out_size) {
    const float* ker = (const float*)d_in[0];
    const float* in  = (const float*)d_in[1];
    const float* in0 = (const float*)d_in[2];
    const float* cw  = (const float*)d_in[3];
    const float* gam = (const float*)d_in[4];
    const float* bet = (const float*)d_in[5];
    const float* mu  = (const float*)d_in[6];
    const float* var = (const float*)d_in[7];
    float* out = (float*)d_out;

    int bs = in_sizes[0] / (9 * HW);   // batch from kernel tensor size

    prep_kernel<<<10, 128>>>(cw, gam, bet, mu, var);

    // Async D2D copy staged weights into __constant__ (graph-capturable).
    void* stage_ptr = nullptr;
    cudaGetSymbolAddress(&stage_ptr, g_stage);
    cudaMemcpyToSymbolAsync(c_all, stage_ptr, 1236 * sizeof(float), 0,
                            cudaMemcpyDeviceToDevice);

    dim3 blk(8, 16);
    dim3 grd(W / 32, NBY_MAIN + NBY_EXTRA, bs);
    cspn_main<<<grd, blk>>>(ker, in, in0, cw, gam, bet, mu, var, out);
}

// round 15
// speedup vs baseline: 1.3695x; 1.3695x over previous
#include <cuda_runtime.h>

#define H 512
#define W 512
#define HW (H * W)
#define BN_EPS 1e-5f
#define RING (4 * W - 4)          // 2044 ring pixels per batch
#define BPX 14                    // border pixels per border block (14*9=126 thr)
#define NBY_MAIN 32               // 512 / 16 rows per main block
#define NBY_EXTRA 10              // 160 border blocks per batch (need 146)

typedef unsigned long long u64;

// Staging (written by prep_kernel) -> copied into __constant__ each launch.
// Layout per tap (12 floats): w0..w7, w8, w8, 0, 0   (slot9 = dup of w8)
//   [0,900)    5x5 weights, 75 taps x 12
//   [900,1224) 3x3 weights, 27 taps x 12
//   [1224,1232) BN shift pairs (8 floats = 4 u64)
//   [1232]     shift[8]
__device__ float g_stage[1236];
__constant__ __align__(16) float c_all[1236];

// ---------------- packed f32x2 helpers ----------------
__device__ __forceinline__ u64 pk(float a, float b) {
    u64 d;
    asm("mov.b64 %0, {%1, %2};" : "=l"(d) : "f"(a), "f"(b));
    return d;
}
__device__ __forceinline__ void upk(u64 d, float& a, float& b) {
    asm("mov.b64 {%0, %1}, %2;" : "=f"(a), "=f"(b) : "l"(d));
}
__device__ __forceinline__ void fma2(u64& c, u64 a, u64 b) {
    asm("fma.rn.f32x2 %0, %1, %2, %0;" : "+l"(c) : "l"(a), "l"(b));
}

// ---------------------------------------------------------------------------
// Kernel 1: prep — one staged entry per thread (10 blocks x 128 >= 1236).
// ---------------------------------------------------------------------------
__global__ void prep_kernel(const float* __restrict__ cw,
                            const float* __restrict__ gam,
                            const float* __restrict__ bet,
                            const float* __restrict__ mu,
                            const float* __restrict__ var) {
    int tid = blockIdx.x * blockDim.x + threadIdx.x;
    if (tid < 900) {
        int t5 = tid / 12, kk = tid % 12;
        if (kk >= 10) { g_stage[tid] = 0.f; return; }
        int k = (kk == 9) ? 8 : kk;             // slot 9 duplicates w8
        int v = t5 % 5, u = (t5 / 5) % 5, c = t5 / 25;
        float s = gam[k] * rsqrtf(var[k] + BN_EPS);
        float sum = 0.f;
#pragma unroll
        for (int ti = 0; ti < 3; ti++) {
            int di = u - ti;
            if (di < 0 || di > 2) continue;
#pragma unroll
            for (int tj = 0; tj < 3; tj++) {
                int dj = v - tj;
                if (dj < 0 || dj > 2) continue;
                int t = ti * 3 + tj;
                if (c == 0 && t >= 4 && t <= 6) continue;   // replaced rows
                sum += cw[((k * 27 + c * 9 + t) * 3 + di) * 3 + dj];
            }
        }
        g_stage[tid] = s * sum;
    } else if (tid < 1224) {
        int i = tid - 900;
        int t3 = i / 12, kk = i % 12;
        if (kk >= 10) { g_stage[tid] = 0.f; return; }
        int k = (kk == 9) ? 8 : kk;
        int v = t3 % 3, u = (t3 / 3) % 3, j = t3 / 9;
        float s = gam[k] * rsqrtf(var[k] + BN_EPS);
        g_stage[tid] = s * cw[((k * 27 + 4 + j) * 3 + u) * 3 + v];
    } else if (tid < 1233) {
        int k = tid - 1224;     // 0..8
        float s = gam[k] * rsqrtf(var[k] + BN_EPS);
        g_stage[tid] = bet[k] - mu[k] * s;
    } else if (tid < 1236) {
        g_stage[tid] = 0.f;
    }
}

// ---------------------------------------------------------------------------
// Row loaders over window [w0-2, w0+5].
//   dup[i] = {v[i], v[i]}   (broadcast data, for k0..7 packed weight pairs)
//   adj[i] = {v[i], v[i+1]} (adjacent-pixel pairs, for packed k8)
// ---------------------------------------------------------------------------
__device__ __forceinline__ void build_pairs(const float v[8], u64 dup[8], u64 adj[7]) {
#pragma unroll
    for (int i = 0; i < 8; i++) dup[i] = pk(v[i], v[i]);
#pragma unroll
    for (int i = 0; i < 7; i++) adj[i] = pk(v[i], v[i + 1]);
}

__device__ __forceinline__ void load_row8_fast(const float* __restrict__ p,
                                               u64 dup[8], u64 adj[7]) {
    float v[8];
    u64 a = *(const u64*)(p - 2);          // v0,v1
    float4 m = *(const float4*)(p);        // v2..v5 (16B aligned)
    u64 c = *(const u64*)(p + 4);          // v6,v7
    upk(a, v[0], v[1]);
    v[2] = m.x; v[3] = m.y; v[4] = m.z; v[5] = m.w;
    upk(c, v[6], v[7]);
    build_pairs(v, dup, adj);
}

__device__ __forceinline__ void load_row8_guard(const float* __restrict__ rowp, int w0,
                                                bool rowok, bool colsafe,
                                                u64 dup[8], u64 adj[7]) {
    if (rowok && colsafe) {
        load_row8_fast(rowp + w0, dup, adj);
        return;
    }
    float v[8];
    if (rowok) {
#pragma unroll
        for (int i = 0; i < 8; i++) {
            int ww = w0 - 2 + i;
            v[i] = (ww >= 0 && ww < W) ? rowp[ww] : 0.f;
        }
    } else {
#pragma unroll
        for (int i = 0; i < 8; i++) v[i] = 0.f;
    }
    build_pairs(v, dup, adj);
}

// Apply one tap's 9 weights from __constant__ at float-offset woff.
// k0..7: packed weight pairs x broadcast data; k8: dup'd weight x pixel pairs.
__device__ __forceinline__ void apply_tap_c(int woff,
                                            const u64 dup[8], const u64 adj[7], int base,
                                            u64 accp[4][4], u64 acc8p[2]) {
    ulonglong2 qa = *(const ulonglong2*)&c_all[woff];       // {w0,w1},{w2,w3}
    ulonglong2 qb = *(const ulonglong2*)&c_all[woff + 4];   // {w4,w5},{w6,w7}
    u64 w8d = *(const u64*)&c_all[woff + 8];                // {w8,w8}
#pragma unroll
    for (int p = 0; p < 4; p++) {
        u64 d = dup[base + p];
        fma2(accp[p][0], qa.x, d);
        fma2(accp[p][1], qa.y, d);
        fma2(accp[p][2], qb.x, d);
        fma2(accp[p][3], qb.y, d);
    }
    fma2(acc8p[0], w8d, adj[base]);       // pixels (0,1)
    fma2(acc8p[1], w8d, adj[base + 2]);   // pixels (2,3)
}

// ---------------------------------------------------------------------------
// Kernel 2: fused main + border.
// ---------------------------------------------------------------------------
__global__ __launch_bounds__(128, 6) void cspn_main(
        const float* __restrict__ ker,
        const float* __restrict__ in,
        const float* __restrict__ in0,
        const float* __restrict__ cw,
        const float* __restrict__ gam,
        const float* __restrict__ bet,
        const float* __restrict__ mu,
        const float* __restrict__ var,
        float* __restrict__ out) {
    const int b = blockIdx.z;
    const int tid = threadIdx.y * 8 + threadIdx.x;

    if (blockIdx.y >= NBY_MAIN) {
        // ================= border path =================
        const int bidx = (blockIdx.y - NBY_MAIN) * 16 + blockIdx.x;
        const int base = bidx * BPX;
        if (base >= RING) return;    // dead block (block-uniform)

        __shared__ float sw[2187];
        __shared__ float pacc[BPX * 9 * 9];

        for (int i = tid; i < 2187; i += 128) sw[i] = cw[i];
        __syncthreads();

        const int px   = tid / 9;
        const int didx = tid % 9;
        const int pos  = base + px;
        const bool active = (tid < 126) && (pos < RING);

        float acc[9];
#pragma unroll
        for (int k = 0; k < 9; k++) acc[k] = 0.f;

        if (active) {
            int h, w;
            if (pos < W)          { h = 0;     w = pos; }
            else if (pos < 2 * W) { h = H - 1; w = pos - W; }
            else {
                int p2 = pos - 2 * W;
                h = 1 + (p2 >> 1);
                w = (p2 & 1) ? (W - 1) : 0;
            }
            const float* inb  = in  + (size_t)b * 3 * HW;
            const float* in0b = in0 + (size_t)b * 3 * HW;
            const int dy = didx / 3 - 1, dx = didx % 3 - 1;
            const int qy = h + dy, qx = w + dx;
            const bool qok = (qy >= 0 && qy < H && qx >= 0 && qx < W);
#pragma unroll
            for (int ch = 0; ch < 27; ch++) {
                float val;
                if (ch >= 4 && ch <= 6) {
                    val = qok ? in0b[(ch - 4) * HW + qy * W + qx] : 0.f;
                } else {
                    int c = ch / 9, t = ch % 9;
                    int py = qy + t / 3 - 1, qx2 = qx + t % 3 - 1;
                    bool pok = qok && (py >= 0 && py < H && qx2 >= 0 && qx2 < W);
                    val = pok ? inb[c * HW + py * W + qx2] : 0.f;
                }
#pragma unroll
                for (int k = 0; k < 9; k++)
                    acc[k] = fmaf(sw[(k * 27 + ch) * 9 + didx], val, acc[k]);
            }
        }
        if (tid < 126) {
#pragma unroll
            for (int k = 0; k < 9; k++) pacc[(px * 9 + didx) * 9 + k] = acc[k];
        }
        __syncthreads();

        if (tid < BPX) {
            int pos2 = base + tid;
            if (pos2 < RING) {
                int hh, ww;
                if (pos2 < W)          { hh = 0;     ww = pos2; }
                else if (pos2 < 2 * W) { hh = H - 1; ww = pos2 - W; }
                else {
                    int p2 = pos2 - 2 * W;
                    hh = 1 + (p2 >> 1);
                    ww = (p2 & 1) ? (W - 1) : 0;
                }
                float r = 0.f;
#pragma unroll
                for (int k = 0; k < 9; k++) {
                    float s = 0.f;
#pragma unroll
                    for (int d = 0; d < 9; d++) s += pacc[(tid * 9 + d) * 9 + k];
                    float sc = gam[k] * rsqrtf(var[k] + BN_EPS);
                    float sh = bet[k] - mu[k] * sc;
                    r = fmaf(ker[((size_t)b * 9 + k) * HW + hh * W + ww],
                             fmaf(sc, s, sh), r);
                }
                out[(size_t)b * HW + hh * W + ww] = r;
            }
        }
        return;
    }

    // ================= main path (weights from __constant__) =================
    const int h  = blockIdx.y * 16 + threadIdx.y;
    const int w0 = blockIdx.x * 32 + threadIdx.x * 4;

    // Seed accumulators with the BN shift (deletes the epilogue adds).
    u64 accp[4][4];
    u64 acc8p[2];
    {
        u64 s0 = *(const u64*)&c_all[1224];
        u64 s1 = *(const u64*)&c_all[1226];
        u64 s2 = *(const u64*)&c_all[1228];
        u64 s3 = *(const u64*)&c_all[1230];
        float sh8 = c_all[1232];
        u64 s8 = pk(sh8, sh8);
#pragma unroll
        for (int p = 0; p < 4; p++) {
            accp[p][0] = s0; accp[p][1] = s1; accp[p][2] = s2; accp[p][3] = s3;
        }
        acc8p[0] = s8; acc8p[1] = s8;
    }

    const float* inb  = in  + (size_t)b * 3 * HW;
    const float* in0b = in0 + (size_t)b * 3 * HW;

    const bool fast = (blockIdx.x >= 1) && (blockIdx.x <= (W / 32) - 2) &&
                      (blockIdx.y >= 1) && (blockIdx.y <= NBY_MAIN - 2);

    if (fast) {
        const float* base5 = inb + (h - 2) * W + w0;
#pragma unroll
        for (int c = 0; c < 3; c++) {
#pragma unroll
            for (int u = 0; u < 5; u++) {
                u64 dup[8], adj[7];
                load_row8_fast(base5 + c * HW + u * W, dup, adj);
#pragma unroll
                for (int tv = 0; tv < 5; tv++)
                    apply_tap_c(((c * 5 + u) * 5 + tv) * 12, dup, adj, tv, accp, acc8p);
            }
        }
        const float* base3 = in0b + (h - 1) * W + w0;
#pragma unroll
        for (int j3 = 0; j3 < 3; j3++) {
#pragma unroll
            for (int u = 0; u < 3; u++) {
                u64 dup[8], adj[7];
                load_row8_fast(base3 + j3 * HW + u * W, dup, adj);
#pragma unroll
                for (int tv = 0; tv < 3; tv++)
                    apply_tap_c(900 + ((j3 * 3 + u) * 3 + tv) * 12, dup, adj, 1 + tv, accp, acc8p);
            }
        }
    } else {
        const bool colsafe = (w0 >= 2) && (w0 + 6 <= W);
#pragma unroll 1
        for (int c = 0; c < 3; c++) {
            const float* inc = inb + c * HW;
#pragma unroll 1
            for (int u = 0; u < 5; u++) {
                int r = h + u - 2;
                u64 dup[8], adj[7];
                load_row8_guard(inc + r * W, w0, (r >= 0 && r < H), colsafe, dup, adj);
#pragma unroll
                for (int tv = 0; tv < 5; tv++)
                    apply_tap_c(((c * 5 + u) * 5 + tv) * 12, dup, adj, tv, accp, acc8p);
            }
        }
#pragma unroll 1
        for (int j3 = 0; j3 < 3; j3++) {
            const float* inc = in0b + j3 * HW;
#pragma unroll 1
            for (int u = 0; u < 3; u++) {
                int r = h + u - 1;
                u64 dup[8], adj[7];
                load_row8_guard(inc + r * W, w0, (r >= 0 && r < H), colsafe, dup, adj);
#pragma unroll
                for (int tv = 0; tv < 3; tv++)
                    apply_tap_c(900 + ((j3 * 3 + u) * 3 + tv) * 12, dup, adj, 1 + tv, accp, acc8p);
            }
        }
    }

    // ---- epilogue: per-pixel dot with kernel (shift already in acc) ----
    const float* kp = ker + (size_t)b * 9 * HW + h * W + w0;
    u64 rp[4] = {0ull, 0ull, 0ull, 0ull};
#pragma unroll
    for (int j = 0; j < 4; j++) {
        const float4 ka = *(const float4*)(kp + (2 * j) * HW);
        const float4 kb = *(const float4*)(kp + (2 * j + 1) * HW);
        fma2(rp[0], pk(ka.x, kb.x), accp[0][j]);
        fma2(rp[1], pk(ka.y, kb.y), accp[1][j]);
        fma2(rp[2], pk(ka.z, kb.z), accp[2][j]);
        fma2(rp[3], pk(ka.w, kb.w), accp[3][j]);
    }
    float res[4];
    {
        const float4 k8 = *(const float4*)(kp + 8 * HW);
        float a80, a81, a82, a83;
        upk(acc8p[0], a80, a81);
        upk(acc8p[1], a82, a83);
        float lo, hi;
        upk(rp[0], lo, hi); res[0] = lo + hi + k8.x * a80;
        upk(rp[1], lo, hi); res[1] = lo + hi + k8.y * a81;
        upk(rp[2], lo, hi); res[2] = lo + hi + k8.z * a82;
        upk(rp[3], lo, hi); res[3] = lo + hi + k8.w * a83;
    }

    // Interior writes only (ring owned by border blocks).
    if (h >= 1 && h <= H - 2) {
        float* op = out + (size_t)b * HW + h * W + w0;
        if (w0 == 0)          { op[1] = res[1]; op[2] = res[2]; op[3] = res[3]; }
        else if (w0 == W - 4) { op[0] = res[0]; op[1] = res[1]; op[2] = res[2]; }
        else                  { *(float4*)op = make_float4(res[0], res[1], res[2], res[3]); }
    }
}

// ---------------------------------------------------------------------------
extern "C" void kernel_launch(void* const* d_in, const int* in_sizes, int n_in,
                              void* d_out, int out_size) {
    const float* ker = (const float*)d_in[0];
    const float* in  = (const float*)d_in[1];
    const float* in0 = (const float*)d_in[2];
    const float* cw  = (const float*)d_in[3];
    const float* gam = (const float*)d_in[4];
    const float* bet = (const float*)d_in[5];
    const float* mu  = (const float*)d_in[6];
    const float* var = (const float*)d_in[7];
    float* out = (float*)d_out;

    int bs = in_sizes[0] / (9 * HW);   // batch from kernel tensor size

    prep_kernel<<<10, 128>>>(cw, gam, bet, mu, var);

    // Async D2D copy staged weights into __constant__ (graph-capturable).
    void* stage_ptr = nullptr;
    cudaGetSymbolAddress(&stage_ptr, g_stage);
    cudaMemcpyToSymbolAsync(c_all, stage_ptr, 1236 * sizeof(float), 0,
                            cudaMemcpyDeviceToDevice);

    dim3 blk(8, 16);
    dim3 grd(W / 32, NBY_MAIN + NBY_EXTRA, bs);
    cspn_main<<<grd, blk>>>(ker, in, in0, cw, gam, bet, mu, var, out);
}